// round 6
// baseline (speedup 1.0000x reference)
#include <cuda_runtime.h>

// MotorLayer: out[j] = sum_i weight[j,i] * input[i, j<3 ? 0 : 1]
// R6: fused kernel, 2048x256 grid-stride stream (best measured), with a
// HIERARCHICAL 2-level completion tree (32 groups x 64 blocks) replacing the
// single-counter finish: kills the 2048-wide single-address atomic burst and
// the 48KB last-block read that cost ~5-6us of serialized tail.

#define N_IN      8388608
#define N4        (N_IN / 4)            // float4 chunks per weight row
#define BLOCKS    2048
#define THREADS   256
#define NWARPS    (THREADS / 32)
#define GSIZE     64                    // blocks per group
#define NGROUPS   (BLOCKS / GSIZE)      // 32

__device__ float g_partials[BLOCKS * 6];        // per-block partials
__device__ float g_group[NGROUPS * 6];          // per-group partials
__device__ unsigned int g_gcount[NGROUPS];      // zero-init; reset by final block
__device__ unsigned int g_fcount;               // zero-init; reset by final block

__global__ __launch_bounds__(THREADS)
void motor_fused(const float4* __restrict__ inpv,   // N4*2 float4 (pairs interleaved)
                 const float4* __restrict__ wv,     // 6 rows x N4 float4
                 float* __restrict__ out)
{
    const int warp = threadIdx.x >> 5;
    const int lane = threadIdx.x & 31;

    float s0 = 0.f, s1 = 0.f, s2 = 0.f, s3 = 0.f, s4 = 0.f, s5 = 0.f;

    const int stride = BLOCKS * THREADS;
    for (int it = blockIdx.x * THREADS + threadIdx.x; it < N4; it += stride) {
        float4 p  = inpv[it * 2 + 0];
        float4 q  = inpv[it * 2 + 1];
        float4 w0 = wv[0 * N4 + it];
        float4 w1 = wv[1 * N4 + it];
        float4 w2 = wv[2 * N4 + it];
        float4 w3 = wv[3 * N4 + it];
        float4 w4 = wv[4 * N4 + it];
        float4 w5 = wv[5 * N4 + it];

        s0 += w0.x * p.x + w0.y * p.z + w0.z * q.x + w0.w * q.z;
        s1 += w1.x * p.x + w1.y * p.z + w1.z * q.x + w1.w * q.z;
        s2 += w2.x * p.x + w2.y * p.z + w2.z * q.x + w2.w * q.z;
        s3 += w3.x * p.y + w3.y * p.w + w3.z * q.y + w3.w * q.w;
        s4 += w4.x * p.y + w4.y * p.w + w4.z * q.y + w4.w * q.w;
        s5 += w5.x * p.y + w5.y * p.w + w5.z * q.y + w5.w * q.w;
    }

    // Warp reduction (fixed pattern, deterministic)
    #pragma unroll
    for (int off = 16; off > 0; off >>= 1) {
        s0 += __shfl_down_sync(0xffffffffu, s0, off);
        s1 += __shfl_down_sync(0xffffffffu, s1, off);
        s2 += __shfl_down_sync(0xffffffffu, s2, off);
        s3 += __shfl_down_sync(0xffffffffu, s3, off);
        s4 += __shfl_down_sync(0xffffffffu, s4, off);
        s5 += __shfl_down_sync(0xffffffffu, s5, off);
    }

    __shared__ float smem[NWARPS][6];
    if (lane == 0) {
        smem[warp][0] = s0; smem[warp][1] = s1; smem[warp][2] = s2;
        smem[warp][3] = s3; smem[warp][4] = s4; smem[warp][5] = s5;
    }
    __syncthreads();

    const int grp = blockIdx.x / GSIZE;

    __shared__ bool is_last_in_group;
    if (threadIdx.x == 0) {
        float t0 = 0.f, t1 = 0.f, t2 = 0.f, t3 = 0.f, t4 = 0.f, t5 = 0.f;
        #pragma unroll
        for (int w = 0; w < NWARPS; w++) {
            t0 += smem[w][0]; t1 += smem[w][1]; t2 += smem[w][2];
            t3 += smem[w][3]; t4 += smem[w][4]; t5 += smem[w][5];
        }
        float* dst = &g_partials[blockIdx.x * 6];
        dst[0] = t0; dst[1] = t1; dst[2] = t2;
        dst[3] = t3; dst[4] = t4; dst[5] = t5;
        __threadfence();                       // publish partials
        unsigned prev = atomicAdd(&g_gcount[grp], 1u);
        is_last_in_group = (prev == GSIZE - 1);
    }
    __syncthreads();
    if (!is_last_in_group) return;

    // ---- Phase 2: group leader reduces its 64 block-partials (1.5 KB, L2-hot).
    // Threads 0..63 each own one block's 6 floats (index order -> deterministic).
    __threadfence();                           // acquire: see all group partials
    float t0 = 0.f, t1 = 0.f, t2 = 0.f, t3 = 0.f, t4 = 0.f, t5 = 0.f;
    if (threadIdx.x < GSIZE) {
        const float* src = &g_partials[(grp * GSIZE + threadIdx.x) * 6];
        t0 = src[0]; t1 = src[1]; t2 = src[2];
        t3 = src[3]; t4 = src[4]; t5 = src[5];
    }
    // reduce over 64 lanes = 2 warps (warps 0 and 1)
    #pragma unroll
    for (int off = 16; off > 0; off >>= 1) {
        t0 += __shfl_down_sync(0xffffffffu, t0, off);
        t1 += __shfl_down_sync(0xffffffffu, t1, off);
        t2 += __shfl_down_sync(0xffffffffu, t2, off);
        t3 += __shfl_down_sync(0xffffffffu, t3, off);
        t4 += __shfl_down_sync(0xffffffffu, t4, off);
        t5 += __shfl_down_sync(0xffffffffu, t5, off);
    }
    if (warp < 2 && lane == 0) {
        smem[warp][0] = t0; smem[warp][1] = t1; smem[warp][2] = t2;
        smem[warp][3] = t3; smem[warp][4] = t4; smem[warp][5] = t5;
    }
    __syncthreads();

    __shared__ bool is_final;
    if (threadIdx.x == 0) {
        float u0 = smem[0][0] + smem[1][0];
        float u1 = smem[0][1] + smem[1][1];
        float u2 = smem[0][2] + smem[1][2];
        float u3 = smem[0][3] + smem[1][3];
        float u4 = smem[0][4] + smem[1][4];
        float u5 = smem[0][5] + smem[1][5];
        float* gdst = &g_group[grp * 6];
        gdst[0] = u0; gdst[1] = u1; gdst[2] = u2;
        gdst[3] = u3; gdst[4] = u4; gdst[5] = u5;
        __threadfence();                       // publish group partial
        unsigned prev = atomicAdd(&g_fcount, 1u);
        is_final = (prev == NGROUPS - 1);
    }
    __syncthreads();
    if (!is_final) return;

    // ---- Phase 3: final block reduces 32 group-partials (768 B) with 1 warp.
    __threadfence();                           // acquire: see all group partials
    if (warp == 0) {
        float f0 = 0.f, f1 = 0.f, f2 = 0.f, f3 = 0.f, f4 = 0.f, f5 = 0.f;
        // 32 lanes, one group each (index order -> deterministic)
        {
            const float* src = &g_group[lane * 6];
            f0 = src[0]; f1 = src[1]; f2 = src[2];
            f3 = src[3]; f4 = src[4]; f5 = src[5];
        }
        #pragma unroll
        for (int off = 16; off > 0; off >>= 1) {
            f0 += __shfl_down_sync(0xffffffffu, f0, off);
            f1 += __shfl_down_sync(0xffffffffu, f1, off);
            f2 += __shfl_down_sync(0xffffffffu, f2, off);
            f3 += __shfl_down_sync(0xffffffffu, f3, off);
            f4 += __shfl_down_sync(0xffffffffu, f4, off);
            f5 += __shfl_down_sync(0xffffffffu, f5, off);
        }
        if (lane == 0) {
            out[0] = f0; out[1] = f1; out[2] = f2;
            out[3] = f3; out[4] = f4; out[5] = f5;
            g_fcount = 0;                       // reset for graph replay
        }
        // reset group counters (all phase-1 work is complete by construction)
        if (lane < NGROUPS) g_gcount[lane] = 0;
    }
}

extern "C" void kernel_launch(void* const* d_in, const int* in_sizes, int n_in,
                              void* d_out, int out_size) {
    const float4* inpv = (const float4*)d_in[0];   // input  [8388608, 2] fp32
    const float4* wv   = (const float4*)d_in[1];   // weight [6, 8388608] fp32
    float* out = (float*)d_out;

    motor_fused<<<BLOCKS, THREADS>>>(inpv, wv, out);
}

// round 7
// speedup vs baseline: 1.1305x; 1.1305x over previous
#include <cuda_runtime.h>
#include <cstdint>

// MotorLayer: out[j] = sum_i weight[j,i] * input[i, j<3 ? 0 : 1]
// R7: TMA (cp.async.bulk) 4-stage smem pipeline. 148 blocks (1/SM) x 288 thr
// (8 consumer warps + 1 producer warp). Per chunk (1024 i): input 8KB + 6x4KB
// weight slices -> 32KB stage. Deep bulk-copy queue replaces per-warp LDG
// latency chains that left DRAM idle 29% of cycles.

#define N_IN     8388608
#define CI       1024                   // i-values per chunk
#define NCHUNK   (N_IN / CI)            // 8192
#define GRID     148
#define CONS_T   256                    // consumer threads (warps 0-7)
#define THREADS  288                    // + producer warp 8
#define NWARPS   (THREADS / 32)         // 9
#define STAGES   4
#define IN_BYTES   (CI * 2 * 4)         // 8192
#define W_BYTES    (CI * 4)             // 4096
#define STAGE_BYTES (IN_BYTES + 6 * W_BYTES)  // 32768
#define SMEM_DYN   (STAGES * STAGE_BYTES)     // 131072

__device__ float g_partials[GRID * 6];
__device__ unsigned int g_count = 0;

// ---- minimal PTX helpers ----
__device__ __forceinline__ uint32_t smem_u32(const void* p) {
    uint32_t a;
    asm("{ .reg .u64 t; cvta.to.shared.u64 t, %1; cvt.u32.u64 %0, t; }" : "=r"(a) : "l"(p));
    return a;
}
#define MBAR_INIT(addr, cnt) \
    asm volatile("mbarrier.init.shared.b64 [%0], %1;" :: "r"(addr), "r"(cnt) : "memory")
#define MBAR_EXPECT_TX(addr, bytes) \
    asm volatile("mbarrier.arrive.expect_tx.shared.b64 _, [%0], %1;" :: "r"(addr), "r"(bytes) : "memory")
#define MBAR_ARRIVE(addr) \
    asm volatile("mbarrier.arrive.shared.b64 _, [%0];" :: "r"(addr) : "memory")
#define MBAR_WAIT(addr, parity) do {                                              \
    asm volatile(                                                                 \
        "{\n\t.reg .pred P1;\n\t"                                                 \
        "WAIT_LOOP_%=:\n\t"                                                       \
        "mbarrier.try_wait.parity.acquire.cta.shared::cta.b64 P1, [%0], %1, 0x989680;\n\t" \
        "@P1 bra.uni WAIT_DONE_%=;\n\t"                                           \
        "bra.uni WAIT_LOOP_%=;\n\t"                                               \
        "WAIT_DONE_%=:\n\t}"                                                      \
        :: "r"(addr), "r"(parity) : "memory");                                    \
} while (0)
#define BULK_G2S(dst, src, bytes, mbar)                                           \
    asm volatile("cp.async.bulk.shared::cluster.global.mbarrier::complete_tx::bytes " \
                 "[%0], [%1], %2, [%3];"                                          \
                 :: "r"(dst), "l"(src), "r"(bytes), "r"(mbar) : "memory")

__global__ __launch_bounds__(THREADS, 1)
void motor_tma(const float* __restrict__ inp,    // [8388608, 2]
               const float* __restrict__ w,      // [6, 8388608]
               float* __restrict__ out)
{
    extern __shared__ char dyn[];
    __shared__ __align__(16) uint64_t mbar[2 * STAGES];   // [full0..full3, empty0..empty3]
    __shared__ float rsm[NWARPS][6];
    __shared__ bool is_last;

    const int tid  = threadIdx.x;
    const int warp = tid >> 5;
    const int lane = tid & 31;
    const uint32_t dyn_base  = smem_u32(dyn);
    const uint32_t mbar_base = smem_u32(mbar);

    if (tid == 0) {
        #pragma unroll
        for (int s = 0; s < STAGES; s++) {
            MBAR_INIT(mbar_base + s * 8, 1);                    // full: producer expect_tx
            MBAR_INIT(mbar_base + (STAGES + s) * 8, CONS_T);    // empty: all consumers arrive
        }
    }
    __syncthreads();

    float s0 = 0.f, s1 = 0.f, s2 = 0.f, s3 = 0.f, s4 = 0.f, s5 = 0.f;

    if (warp == 8) {
        // ---- producer warp: lane 0 issues bulk copies, ring of STAGES ----
        if (lane == 0) {
            int stage = 0, phase = 1;   // phase=1: first empty-wait passes immediately
            for (int k = blockIdx.x; k < NCHUNK; k += GRID) {
                const uint32_t emp = mbar_base + (STAGES + stage) * 8;
                const uint32_t ful = mbar_base + stage * 8;
                MBAR_WAIT(emp, phase);
                MBAR_EXPECT_TX(ful, STAGE_BYTES);
                const uint32_t sb = dyn_base + stage * STAGE_BYTES;
                BULK_G2S(sb, inp + (size_t)k * CI * 2, IN_BYTES, ful);
                #pragma unroll
                for (int r = 0; r < 6; r++)
                    BULK_G2S(sb + IN_BYTES + r * W_BYTES,
                             w + (size_t)r * N_IN + (size_t)k * CI, W_BYTES, ful);
                if (++stage == STAGES) { stage = 0; phase ^= 1; }
            }
        }
    } else {
        // ---- consumer warps 0-7 (256 threads): one float4-group each per chunk ----
        int stage = 0, phase = 0;
        for (int k = blockIdx.x; k < NCHUNK; k += GRID) {
            const uint32_t ful = mbar_base + stage * 8;
            const uint32_t emp = mbar_base + (STAGES + stage) * 8;
            MBAR_WAIT(ful, phase);

            const char* sb = dyn + stage * STAGE_BYTES;
            const float4* sin = (const float4*)sb;                 // 512 float4
            const float4* sw  = (const float4*)(sb + IN_BYTES);    // 6 x 256 float4

            float4 p  = sin[2 * tid + 0];
            float4 q  = sin[2 * tid + 1];
            float4 w0 = sw[0 * (CI / 4) + tid];
            float4 w1 = sw[1 * (CI / 4) + tid];
            float4 w2 = sw[2 * (CI / 4) + tid];
            float4 w3 = sw[3 * (CI / 4) + tid];
            float4 w4 = sw[4 * (CI / 4) + tid];
            float4 w5 = sw[5 * (CI / 4) + tid];

            s0 += w0.x * p.x + w0.y * p.z + w0.z * q.x + w0.w * q.z;
            s1 += w1.x * p.x + w1.y * p.z + w1.z * q.x + w1.w * q.z;
            s2 += w2.x * p.x + w2.y * p.z + w2.z * q.x + w2.w * q.z;
            s3 += w3.x * p.y + w3.y * p.w + w3.z * q.y + w3.w * q.w;
            s4 += w4.x * p.y + w4.y * p.w + w4.z * q.y + w4.w * q.w;
            s5 += w5.x * p.y + w5.y * p.w + w5.z * q.y + w5.w * q.w;

            MBAR_ARRIVE(emp);           // release: my reads done, buffer reusable
            if (++stage == STAGES) { stage = 0; phase ^= 1; }
        }

        // warp reduction (fixed pattern)
        #pragma unroll
        for (int off = 16; off > 0; off >>= 1) {
            s0 += __shfl_down_sync(0xffffffffu, s0, off);
            s1 += __shfl_down_sync(0xffffffffu, s1, off);
            s2 += __shfl_down_sync(0xffffffffu, s2, off);
            s3 += __shfl_down_sync(0xffffffffu, s3, off);
            s4 += __shfl_down_sync(0xffffffffu, s4, off);
            s5 += __shfl_down_sync(0xffffffffu, s5, off);
        }
        if (lane == 0) {
            rsm[warp][0] = s0; rsm[warp][1] = s1; rsm[warp][2] = s2;
            rsm[warp][3] = s3; rsm[warp][4] = s4; rsm[warp][5] = s5;
        }
    }
    __syncthreads();

    if (tid == 0) {
        float t0 = 0.f, t1 = 0.f, t2 = 0.f, t3 = 0.f, t4 = 0.f, t5 = 0.f;
        #pragma unroll
        for (int wr = 0; wr < 8; wr++) {
            t0 += rsm[wr][0]; t1 += rsm[wr][1]; t2 += rsm[wr][2];
            t3 += rsm[wr][3]; t4 += rsm[wr][4]; t5 += rsm[wr][5];
        }
        float* dst = &g_partials[blockIdx.x * 6];
        dst[0] = t0; dst[1] = t1; dst[2] = t2;
        dst[3] = t3; dst[4] = t4; dst[5] = t5;
        __threadfence();
        unsigned prev = atomicAdd(&g_count, 1u);
        is_last = (prev == GRID - 1);
    }
    __syncthreads();
    if (!is_last) return;

    // final block: reduce GRID x 6 partials (3.5 KB, L2-hot)
    __threadfence();
    float t0 = 0.f, t1 = 0.f, t2 = 0.f, t3 = 0.f, t4 = 0.f, t5 = 0.f;
    for (int b = tid; b < GRID; b += THREADS) {
        const float* src = &g_partials[b * 6];
        t0 += src[0]; t1 += src[1]; t2 += src[2];
        t3 += src[3]; t4 += src[4]; t5 += src[5];
    }
    #pragma unroll
    for (int off = 16; off > 0; off >>= 1) {
        t0 += __shfl_down_sync(0xffffffffu, t0, off);
        t1 += __shfl_down_sync(0xffffffffu, t1, off);
        t2 += __shfl_down_sync(0xffffffffu, t2, off);
        t3 += __shfl_down_sync(0xffffffffu, t3, off);
        t4 += __shfl_down_sync(0xffffffffu, t4, off);
        t5 += __shfl_down_sync(0xffffffffu, t5, off);
    }
    __syncthreads();
    if (lane == 0) {
        rsm[warp][0] = t0; rsm[warp][1] = t1; rsm[warp][2] = t2;
        rsm[warp][3] = t3; rsm[warp][4] = t4; rsm[warp][5] = t5;
    }
    __syncthreads();
    if (tid == 0) {
        float r0 = 0.f, r1 = 0.f, r2 = 0.f, r3 = 0.f, r4 = 0.f, r5 = 0.f;
        #pragma unroll
        for (int wr = 0; wr < NWARPS; wr++) {
            r0 += rsm[wr][0]; r1 += rsm[wr][1]; r2 += rsm[wr][2];
            r3 += rsm[wr][3]; r4 += rsm[wr][4]; r5 += rsm[wr][5];
        }
        out[0] = r0; out[1] = r1; out[2] = r2;
        out[3] = r3; out[4] = r4; out[5] = r5;
        g_count = 0;   // reset for graph replay
    }
}

extern "C" void kernel_launch(void* const* d_in, const int* in_sizes, int n_in,
                              void* d_out, int out_size) {
    const float* inp = (const float*)d_in[0];   // input  [8388608, 2] fp32
    const float* w   = (const float*)d_in[1];   // weight [6, 8388608] fp32
    float* out = (float*)d_out;

    cudaFuncSetAttribute(motor_tma, cudaFuncAttributeMaxDynamicSharedMemorySize, SMEM_DYN);
    motor_tma<<<GRID, THREADS, SMEM_DYN>>>(inp, w, out);
}